// round 5
// baseline (speedup 1.0000x reference)
#include <cuda_runtime.h>
#include <cuda_bf16.h>

#define NN 9216
#define WW 96
#define NB 8192
#define CAP 32

// Scratch (no cudaMalloc allowed). g_hist re-zeroed by scan_kernel each
// replay so every call sees clean state.
__device__ unsigned      g_hist[NB];
__device__ unsigned      g_binstart[NB];
__device__ unsigned      g_bincnt[NB];
__device__ unsigned      g_list[NB * CAP];
__device__ unsigned char g_keep[NN];

// ---------------------------------------------------------------------------
// Bucket rank stage 1 (proven R3)
// ---------------------------------------------------------------------------
__global__ void __launch_bounds__(256) hist_kernel(const float* __restrict__ cls) {
    int c = blockIdx.x * 256 + threadIdx.x;
    float s = cls[c];
    int bin = min((int)(s * 8192.0f), NB - 1);
    unsigned slot = atomicAdd(&g_hist[bin], 1u);
    if (slot < CAP) g_list[bin * CAP + slot] = (unsigned)c;
}

// ---------------------------------------------------------------------------
// Bucket rank stage 2 (proven R3)
// ---------------------------------------------------------------------------
__global__ void __launch_bounds__(1024) scan_kernel() {
    __shared__ unsigned tot[1024];
    int t = threadIdx.x;
    unsigned v[8], sum = 0;
    #pragma unroll
    for (int i = 0; i < 8; i++) { v[i] = g_hist[t * 8 + i]; sum += v[i]; }
    tot[t] = sum;
    __syncthreads();
    for (int off = 1; off < 1024; off <<= 1) {
        unsigned x = (t >= off) ? tot[t - off] : 0u;
        __syncthreads();
        tot[t] += x;
        __syncthreads();
    }
    unsigned run = t ? tot[t - 1] : 0u;
    #pragma unroll
    for (int i = 0; i < 8; i++) {
        run += v[i];
        g_binstart[t * 8 + i] = NN - run;
        g_bincnt[t * 8 + i]   = v[i];
        g_hist[t * 8 + i]     = 0;
    }
}

// ---------------------------------------------------------------------------
// NMS: event-driven topological greedy. Each cell has a counter of earlier
// valid qualifying neighbors; deciders notify later neighbors (suppress-bit
// then counter decrement, fenced). Counter==0 => fate = suppressed bit.
// Exact integer geometry (boxes 21x21; quals from x%3,y%3) — same as R3.
// ---------------------------------------------------------------------------
__global__ void __launch_bounds__(1024, 1) nms_kernel(const float* __restrict__ cls) {
    __shared__ float    sc[NN];
    __shared__ unsigned cnt1w[NN / 8], cnt2w[NN / 8];   // nibble-packed counters
    __shared__ unsigned supp1w[NN / 32], supp2w[NN / 32];

    const int t  = threadIdx.x;
    const int tx = t & 31, ty = t >> 5;
    const int x0 = 3 * tx, y0 = 3 * ty;

    for (int i = t; i < NN / 8; i += 1024) { cnt1w[i] = 0; cnt2w[i] = 0; }
    if (t < NN / 32) { supp1w[t] = 0; supp2w[t] = 0; }
    #pragma unroll
    for (int k = 0; k < 9; k++) sc[t + k * 1024] = cls[t + k * 1024];
    __syncthreads();

    // ---- Build: per-cell earlier counts + later masks ----
    // Offset table (bit o): OFF = {-192,-97,-96,-95,-2,-1,+1,+2,+95,+96,+97,+192}
    unsigned short l1[9];   // 12-bit later masks, pass 1
    unsigned char  l2[9];   // 4-bit later masks (bits: -96,-1,+1,+96), pass 2
    unsigned pend1 = 0;

    #pragma unroll
    for (int k = 0; k < 9; k++) {
        int ry = k / 3, cx = k % 3;
        int x = x0 + cx, y = y0 + ry;
        int c = y * WW + x;
        float s = sc[c];
        unsigned L1 = 0, L2 = 0, e1 = 0, e2 = 0;
        if (s > 0.6f) {
            pend1 |= 1u << k;
            int xm = x % 3, ym = y % 3;
            // EDGE(o): for qualifying in-bounds neighbor n:
            //   valid(n) ? (earlier(n,c) ? e++ : L|=bit) : nothing
            #define EDGE1(o, OFFV, COND)  do { if (COND) {                         \
                int n = c + (OFFV); float sn = sc[n];                              \
                if (sn > 0.6f) {                                                   \
                    bool ne = (sn > s) || (sn == s && (OFFV) < 0);                 \
                    if (ne) e1++; else L1 |= 1u << (o); } } } while (0)
            EDGE1(0,  -192, y > 1  && ym == 1);
            EDGE1(1,  -97,  x > 0  && y > 0  && !(xm == 2 && ym == 2));
            EDGE1(2,  -96,  y > 0);
            EDGE1(3,  -95,  x < 95 && y > 0  && !(xm == 1 && ym == 2));
            EDGE1(4,  -2,   x > 1  && xm == 1);
            EDGE1(5,  -1,   x > 0);
            EDGE1(6,  +1,   x < 95);
            EDGE1(7,  +2,   x < 94 && xm == 2);
            EDGE1(8,  +95,  x > 0  && y < 95 && !(xm == 2 && ym == 1));
            EDGE1(9,  +96,  y < 95);
            EDGE1(10, +97,  x < 95 && y < 95 && !(xm == 1 && ym == 1));
            EDGE1(11, +192, y < 94 && ym == 2);
            #undef EDGE1
            #define EDGE2(b, OFFV, COND)  do { if (COND) {                         \
                int n = c + (OFFV); float sn = sc[n];                              \
                if (sn > 0.6f) {                                                   \
                    bool ne = (sn > s) || (sn == s && (OFFV) < 0);                 \
                    if (ne) e2++; else L2 |= 1u << (b); } } } while (0)
            EDGE2(0, -96, y > 0  && ym != 2);
            EDGE2(1, -1,  x > 0  && xm != 2);
            EDGE2(2, +1,  x < 95 && xm != 1);
            EDGE2(3, +96, y < 95 && ym != 1);
            #undef EDGE2
            if (e1) atomicAdd(&cnt1w[c >> 3], e1 << ((c & 7) * 4));
            if (e2) atomicAdd(&cnt2w[c >> 3], e2 << ((c & 7) * 4));
        }
        l1[k] = (unsigned short)L1;
        l2[k] = (unsigned char)L2;
    }
    __syncthreads();

    volatile unsigned* vc1 = cnt1w;
    volatile unsigned* vc2 = cnt2w;
    volatile unsigned* vs1 = supp1w;
    volatile unsigned* vs2 = supp2w;

    static const int OFF1[12] = {-192, -97, -96, -95, -2, -1, 1, 2, 95, 96, 97, 192};
    static const int OFF2[4]  = {-96, -1, 1, 96};

    unsigned pend2 = 0, keep9 = 0;

    while (pend1 | pend2) {
        bool prog = false;
        #pragma unroll
        for (int k = 0; k < 9; k++) {
            if (pend1 & (1u << k)) {
                int c = (y0 + k / 3) * WW + x0 + (k % 3);
                if (((vc1[c >> 3] >> ((c & 7) * 4)) & 15u) == 0u) {
                    __threadfence_block();
                    bool sup = (vs1[c >> 5] >> (c & 31)) & 1u;
                    unsigned LL = l1[k];
                    if (!sup) {          // kept in pass 1
                        #pragma unroll
                        for (int o = 0; o < 12; o++)
                            if (LL & (1u << o)) {
                                int m = c + OFF1[o];
                                atomicOr(&supp1w[m >> 5], 1u << (m & 31));
                            }
                        __threadfence_block();
                        #pragma unroll
                        for (int o = 0; o < 12; o++)
                            if (LL & (1u << o)) {
                                int m = c + OFF1[o];
                                atomicAdd(&cnt1w[m >> 3], 0u - (1u << ((m & 7) * 4)));
                            }
                        pend2 |= 1u << k;
                    } else {             // suppressed: notify pass1 + pass2 lists
                        #pragma unroll
                        for (int o = 0; o < 12; o++)
                            if (LL & (1u << o)) {
                                int m = c + OFF1[o];
                                atomicAdd(&cnt1w[m >> 3], 0u - (1u << ((m & 7) * 4)));
                            }
                        unsigned L2m = l2[k];
                        #pragma unroll
                        for (int b = 0; b < 4; b++)
                            if (L2m & (1u << b)) {
                                int m = c + OFF2[b];
                                atomicAdd(&cnt2w[m >> 3], 0u - (1u << ((m & 7) * 4)));
                            }
                    }
                    pend1 &= ~(1u << k);
                    prog = true;
                }
            }
        }
        #pragma unroll
        for (int k = 0; k < 9; k++) {
            if (pend2 & (1u << k)) {
                int c = (y0 + k / 3) * WW + x0 + (k % 3);
                if (((vc2[c >> 3] >> ((c & 7) * 4)) & 15u) == 0u) {
                    __threadfence_block();
                    bool sup = (vs2[c >> 5] >> (c & 31)) & 1u;
                    unsigned L2m = l2[k];
                    if (!sup) {
                        keep9 |= 1u << k;
                        #pragma unroll
                        for (int b = 0; b < 4; b++)
                            if (L2m & (1u << b)) {
                                int m = c + OFF2[b];
                                atomicOr(&supp2w[m >> 5], 1u << (m & 31));
                            }
                        __threadfence_block();
                    }
                    #pragma unroll
                    for (int b = 0; b < 4; b++)
                        if (L2m & (1u << b)) {
                            int m = c + OFF2[b];
                            atomicAdd(&cnt2w[m >> 3], 0u - (1u << ((m & 7) * 4)));
                        }
                    pend2 &= ~(1u << k);
                    prog = true;
                }
            }
        }
        if (!prog) __nanosleep(20);
    }

    #pragma unroll
    for (int k = 0; k < 9; k++) {
        int c = (y0 + k / 3) * WW + x0 + (k % 3);
        g_keep[c] = (keep9 >> k) & 1u;
    }
}

// ---------------------------------------------------------------------------
// Epilogue (proven R3)
// ---------------------------------------------------------------------------
__global__ void __launch_bounds__(256) epi_kernel(const float* __restrict__ cls,
                                                  const float* __restrict__ reg,
                                                  float* __restrict__ out) {
    const int c = blockIdx.x * 256 + threadIdx.x;
    float s  = cls[c];
    int bin  = min((int)(s * 8192.0f), NB - 1);
    unsigned rank = g_binstart[bin];
    unsigned cnt  = min(g_bincnt[bin], (unsigned)CAP);
    for (unsigned j = 0; j < cnt; j++) {
        int idx = (int)g_list[bin * CAP + j];
        float sj = cls[idx];
        rank += (sj > s) || (sj == s && idx < c);
    }
    float kq = g_keep[c] ? 1.0f : 0.0f;
    int x = c % WW, y = c / WW;
    float X1 = rintf((2.0f * x) / 0.6f);
    float X2 = rintf((2.0f * x + 12.0f) / 0.6f);
    float Y1 = rintf((2.0f * y) / 0.6f);
    float Y2 = rintf((2.0f * y + 12.0f) / 0.6f);
    float bw = X2 - X1 + 1.0f;
    float bh = Y2 - Y1 + 1.0f;
    float4 d = ((const float4*)reg)[c];
    float* o = out + (int)rank * 5;
    o[0] = (X1 + d.x * bw) * kq;
    o[1] = (Y1 + d.y * bh) * kq;
    o[2] = (X2 + d.z * bw) * kq;
    o[3] = (Y2 + d.w * bh) * kq;
    o[4] = s * kq;
}

extern "C" void kernel_launch(void* const* d_in, const int* in_sizes, int n_in,
                              void* d_out, int out_size) {
    const float* cls = (const float*)d_in[0];
    const float* reg = (const float*)d_in[1];
    if (n_in >= 2 && in_sizes[0] > in_sizes[1]) {   // defensive: metadata order
        const float* t = cls; cls = reg; reg = t;
    }
    float* out = (float*)d_out;

    hist_kernel<<<36, 256>>>(cls);
    scan_kernel<<<1, 1024>>>();
    nms_kernel<<<1, 1024>>>(cls);
    epi_kernel<<<36, 256>>>(cls, reg, out);
}

// round 8
// speedup vs baseline: 1.3614x; 1.3614x over previous
#include <cuda_runtime.h>
#include <cuda_bf16.h>

#define NN 9216
#define WW 96
#define NB 8192
#define CAP 32

// Global scratch (no cudaMalloc allowed). g_hist starts zeroed (static init)
// and is re-zeroed inside the kernel each call after being read.
__device__ unsigned       g_hist[NB];
__device__ unsigned       g_binstart[NB];
__device__ unsigned       g_bincnt[NB];
__device__ unsigned short g_list[NB * CAP];

__global__ void __launch_bounds__(1024, 1) fused_kernel(const float* __restrict__ cls,
                                                        const float* __restrict__ reg,
                                                        float* __restrict__ out) {
    // STATIC shared only — hot fixpoint arrays must compile to LDS/ATOMS
    // (R4 lesson: computed pointers into dynamic shared => generic ATOM/LD, 2x slower).
    __shared__ float    sc[NN];                                   // 36864 B
    __shared__ unsigned dec1[384], kept1[384], dec2[384], kept2[384]; // 6144 B
    __shared__ unsigned scantmp[1024];                            //  4096 B  => 47104 B

    const int t  = threadIdx.x;
    const int tx = t & 31, ty = t >> 5;
    const int x0 = 3 * tx, y0 = 3 * ty;
    const int w  = x0 >> 5, sh = x0 & 31;

    // ---- Phase 0: zero NMS bit arrays ----
    if (t < 384) { dec1[t] = 0; kept1[t] = 0; dec2[t] = 0; kept2[t] = 0; }

    // ---- Phase 1: load scores to shared; histogram + tie lists in global L2 ----
    // bin = (int)(s*8192) is monotone in s; ties resolved exactly in epilogue.
    #pragma unroll
    for (int k = 0; k < 9; k++) {
        int c = t + k * 1024;
        float s = cls[c];
        sc[c] = s;
        int bin = min((int)(s * 8192.0f), NB - 1);
        unsigned slot = atomicAdd(&g_hist[bin], 1u);
        if (slot < CAP) g_list[bin * CAP + slot] = (unsigned short)c;
    }
    __syncthreads();   // sc + hist complete (syncthreads fences block's global writes)

    // ---- Phase 2: 8192-bin prefix scan; binstart = #elems in higher bins ----
    {
        unsigned v[8], sum = 0;
        #pragma unroll
        for (int i = 0; i < 8; i++) { v[i] = g_hist[t * 8 + i]; sum += v[i]; }
        scantmp[t] = sum;
        __syncthreads();
        for (int off = 1; off < 1024; off <<= 1) {
            unsigned x = (t >= off) ? scantmp[t - off] : 0u;
            __syncthreads();
            scantmp[t] += x;
            __syncthreads();
        }
        unsigned run = t ? scantmp[t - 1] : 0u;
        #pragma unroll
        for (int i = 0; i < 8; i++) {
            run += v[i];
            g_binstart[t * 8 + i] = NN - run;
            g_bincnt[t * 8 + i]   = v[i];
            g_hist[t * 8 + i]     = 0;      // clean for next graph replay
        }
    }

    // ---- Phase 3: build NMS masks (exact integer geometry, 21x21 boxes) ----
    unsigned m1[9];
    unsigned long long m2all = 0;   // 4 bits/cell: up,left,right,down (thr 0.7)
    unsigned pend = 0;
    #pragma unroll
    for (int k = 0; k < 9; k++) {
        int ry = k / 3, cx = k % 3;
        int x = x0 + cx, y = y0 + ry;
        int c = y * WW + x;
        float s = sc[c];
        unsigned mm1 = 0, n2 = 0;
        if (s > 0.6f) {
            pend |= 1u << k;
            int xm = x % 3, ym = y % 3;
            #define EARLIER(n) (sc[(n)] > s || (sc[(n)] == s && (n) < c))
            if (x > 0  && EARLIER(c - 1))  { mm1 |= 1u << 11; if (xm != 2) n2 |= 2u; }
            if (x < 95 && EARLIER(c + 1))  { mm1 |= 1u << 13; if (xm != 1) n2 |= 4u; }
            if (y > 0  && EARLIER(c - 96)) { mm1 |= 1u << 7;  if (ym != 2) n2 |= 1u; }
            if (y < 95 && EARLIER(c + 96)) { mm1 |= 1u << 17; if (ym != 1) n2 |= 8u; }
            if (x > 1  && xm == 1 && EARLIER(c - 2))   mm1 |= 1u << 10;
            if (x < 94 && xm == 2 && EARLIER(c + 2))   mm1 |= 1u << 14;
            if (y > 1  && ym == 1 && EARLIER(c - 192)) mm1 |= 1u << 2;
            if (y < 94 && ym == 2 && EARLIER(c + 192)) mm1 |= 1u << 22;
            bool sxp4 = (xm == 1), sxm4 = (xm == 2), syp4 = (ym == 1), sym4 = (ym == 2);
            if (x > 0  && y > 0  && !(sxm4 && sym4) && EARLIER(c - 97)) mm1 |= 1u << 6;
            if (x < 95 && y > 0  && !(sxp4 && sym4) && EARLIER(c - 95)) mm1 |= 1u << 8;
            if (x > 0  && y < 95 && !(sxm4 && syp4) && EARLIER(c + 95)) mm1 |= 1u << 16;
            if (x < 95 && y < 95 && !(sxp4 && syp4) && EARLIER(c + 97)) mm1 |= 1u << 18;
            #undef EARLIER
        } else {
            int p = x + 2;
            atomicOr(&dec1[y * 4 + (p >> 5)], 1u << (p & 31));
            atomicOr(&dec2[y * 4 + (p >> 5)], 1u << (p & 31));
        }
        m1[k] = mm1;
        m2all |= (unsigned long long)n2 << (4 * k);
    }
    __syncthreads();   // all init bits + scan results visible before spinning

    // ---- Phase 4: lock-free monotone fixpoint (verbatim R3 engine + backoff) ----
    unsigned p1 = pend, p2 = pend;
    unsigned slp = 32;
    while (p1 | p2) {
        bool prog = false;

        if (p1) {
            unsigned dw[7], kw[7];
            #pragma unroll
            for (int r = 0; r < 7; r++) {
                int ry = y0 - 2 + r;
                if ((unsigned)ry < WW) {
                    int base = ry * 4 + w;
                    unsigned dlo = ((volatile unsigned*)dec1)[base];
                    unsigned dhi = ((volatile unsigned*)dec1)[base + 1];
                    unsigned klo = ((volatile unsigned*)kept1)[base];
                    unsigned khi = ((volatile unsigned*)kept1)[base + 1];
                    dw[r] = __funnelshift_r(dlo, dhi, sh) & 0x1FFu;
                    kw[r] = __funnelshift_r(klo, khi, sh) & 0x1FFu;
                } else { dw[r] = 0; kw[r] = 0; }
            }
            #pragma unroll
            for (int k = 0; k < 9; k++) {
                if (!(p1 & (1u << k))) continue;
                int ry = k / 3, cx = k % 3;
                unsigned mm = m1[k], supp = 0, und = 0;
                #pragma unroll
                for (int r = 0; r < 5; r++) {
                    unsigned mrow = (mm >> (5 * r)) & 31u;
                    supp |= mrow & (kw[ry + r] >> cx);
                    und  |= mrow & ((~dw[ry + r]) >> cx);
                }
                int x = x0 + cx, y = y0 + ry, p = x + 2;
                if (supp) {
                    atomicOr(&dec1[y * 4 + (p >> 5)], 1u << (p & 31));
                    atomicOr(&dec2[y * 4 + (p >> 5)], 1u << (p & 31));
                    dw[ry + 2] |= 1u << (cx + 2);
                    p1 &= ~(1u << k); p2 &= ~(1u << k); prog = true;
                } else if (!und) {
                    atomicOr(&dec1[y * 4 + (p >> 5)],  1u << (p & 31));
                    atomicOr(&kept1[y * 4 + (p >> 5)], 1u << (p & 31));
                    dw[ry + 2] |= 1u << (cx + 2);
                    kw[ry + 2] |= 1u << (cx + 2);
                    p1 &= ~(1u << k); prog = true;
                }
            }
        }

        unsigned ready = p2 & ~p1;
        if (ready) {
            unsigned dw[7], kw[7];
            #pragma unroll
            for (int r = 0; r < 7; r++) {
                int ry = y0 - 2 + r;
                if ((unsigned)ry < WW) {
                    int base = ry * 4 + w;
                    unsigned dlo = ((volatile unsigned*)dec2)[base];
                    unsigned dhi = ((volatile unsigned*)dec2)[base + 1];
                    unsigned klo = ((volatile unsigned*)kept2)[base];
                    unsigned khi = ((volatile unsigned*)kept2)[base + 1];
                    dw[r] = __funnelshift_r(dlo, dhi, sh) & 0x1FFu;
                    kw[r] = __funnelshift_r(klo, khi, sh) & 0x1FFu;
                } else { dw[r] = 0; kw[r] = 0; }
            }
            #pragma unroll
            for (int k = 0; k < 9; k++) {
                if (!(ready & (1u << k))) continue;
                int ry = k / 3, cx = k % 3;
                unsigned n2 = (unsigned)(m2all >> (4 * k)) & 15u;
                unsigned supp =
                      ((n2 >> 0) & (kw[ry + 1] >> (cx + 2)))
                    | ((n2 >> 1) & (kw[ry + 2] >> (cx + 1)))
                    | ((n2 >> 2) & (kw[ry + 2] >> (cx + 3)))
                    | ((n2 >> 3) & (kw[ry + 3] >> (cx + 2)));
                unsigned und =
                      ((n2 >> 0) & ((~dw[ry + 1]) >> (cx + 2)))
                    | ((n2 >> 1) & ((~dw[ry + 2]) >> (cx + 1)))
                    | ((n2 >> 2) & ((~dw[ry + 2]) >> (cx + 3)))
                    | ((n2 >> 3) & ((~dw[ry + 3]) >> (cx + 2)));
                int x = x0 + cx, y = y0 + ry, p = x + 2;
                if (supp & 1u) {
                    atomicOr(&dec2[y * 4 + (p >> 5)], 1u << (p & 31));
                    p2 &= ~(1u << k); prog = true;
                } else if (!(und & 1u)) {
                    atomicOr(&dec2[y * 4 + (p >> 5)],  1u << (p & 31));
                    atomicOr(&kept2[y * 4 + (p >> 5)], 1u << (p & 31));
                    p2 &= ~(1u << k); prog = true;
                }
            }
        }

        if (!prog) { __nanosleep(slp); slp = min(slp * 2u, 256u); }
        else slp = 32;
    }
    __syncthreads();   // all cells decided; kept2 is the final keep map

    // ---- Phase 5: epilogue (rank via L2 + shared ties, regress, scatter) ----
    #pragma unroll
    for (int k = 0; k < 9; k++) {
        int c = t + k * 1024;
        float s = sc[c];
        int bin = min((int)(s * 8192.0f), NB - 1);
        unsigned rank = g_binstart[bin];
        unsigned cnt  = g_bincnt[bin];
        if (cnt <= CAP) {
            for (unsigned j = 0; j < cnt; j++) {
                int idx = (int)g_list[bin * CAP + j];
                float sj = sc[idx];
                rank += (sj > s) || (sj == s && idx < c);
            }
        } else {            // overflow fallback: exact recount from shared
            rank = 0;
            for (int j = 0; j < NN; j++) {
                float sj = sc[j];
                rank += (sj > s) || (sj == s && j < c);
            }
        }
        int x = c % WW, y = c / WW, p = x + 2;
        float kq = ((kept2[y * 4 + (p >> 5)] >> (p & 31)) & 1u) ? 1.0f : 0.0f;
        float X1 = rintf((2.0f * x) / 0.6f);
        float X2 = rintf((2.0f * x + 12.0f) / 0.6f);
        float Y1 = rintf((2.0f * y) / 0.6f);
        float Y2 = rintf((2.0f * y + 12.0f) / 0.6f);
        float bw = X2 - X1 + 1.0f;
        float bh = Y2 - Y1 + 1.0f;
        float4 d = ((const float4*)reg)[c];
        float* o = out + (int)rank * 5;
        o[0] = (X1 + d.x * bw) * kq;
        o[1] = (Y1 + d.y * bh) * kq;
        o[2] = (X2 + d.z * bw) * kq;
        o[3] = (Y2 + d.w * bh) * kq;
        o[4] = s * kq;
    }
}

extern "C" void kernel_launch(void* const* d_in, const int* in_sizes, int n_in,
                              void* d_out, int out_size) {
    const float* cls = (const float*)d_in[0];
    const float* reg = (const float*)d_in[1];
    if (n_in >= 2 && in_sizes[0] > in_sizes[1]) {   // defensive: metadata order
        const float* t = cls; cls = reg; reg = t;
    }
    float* out = (float*)d_out;

    fused_kernel<<<1, 1024>>>(cls, reg, out);
}

// round 9
// speedup vs baseline: 2.3286x; 1.7104x over previous
#include <cuda_runtime.h>
#include <cuda_bf16.h>

#define NN 9216
#define WW 96
#define NB 8192
#define CAP 32

// Scratch (no cudaMalloc allowed). g_hist re-zeroed by scan_kernel each
// replay so every call sees clean state.
__device__ unsigned      g_hist[NB];
__device__ unsigned      g_binstart[NB];
__device__ unsigned      g_bincnt[NB];
__device__ unsigned      g_list[NB * CAP];
__device__ unsigned char g_keep[NN];

// ---------------------------------------------------------------------------
// Bucket rank stage 1 (proven R3)
// ---------------------------------------------------------------------------
__global__ void __launch_bounds__(256) hist_kernel(const float* __restrict__ cls) {
    int c = blockIdx.x * 256 + threadIdx.x;
    float s = cls[c];
    int bin = min((int)(s * 8192.0f), NB - 1);
    unsigned slot = atomicAdd(&g_hist[bin], 1u);
    if (slot < CAP) g_list[bin * CAP + slot] = (unsigned)c;
}

// ---------------------------------------------------------------------------
// Bucket rank stage 2 (proven R3)
// ---------------------------------------------------------------------------
__global__ void __launch_bounds__(1024) scan_kernel() {
    __shared__ unsigned tot[1024];
    int t = threadIdx.x;
    unsigned v[8], sum = 0;
    #pragma unroll
    for (int i = 0; i < 8; i++) { v[i] = g_hist[t * 8 + i]; sum += v[i]; }
    tot[t] = sum;
    __syncthreads();
    for (int off = 1; off < 1024; off <<= 1) {
        unsigned x = (t >= off) ? tot[t - off] : 0u;
        __syncthreads();
        tot[t] += x;
        __syncthreads();
    }
    unsigned run = t ? tot[t - 1] : 0u;
    #pragma unroll
    for (int i = 0; i < 8; i++) {
        run += v[i];
        g_binstart[t * 8 + i] = NN - run;
        g_bincnt[t * 8 + i]   = v[i];
        g_hist[t * 8 + i]     = 0;
    }
}

// ---------------------------------------------------------------------------
// NMS: deterministic barrier-round engine over R3's tiled bit-packed state.
// Each round: 2x (pass1 sweep + pass2 sweep), then __syncthreads_and.
// No volatile, no nanosleep — __syncthreads orders rounds; intra-round
// visibility of shared writes only accelerates (monotone decisions).
// Exact integer geometry (boxes 21x21; qualifiers from x%3,y%3) — proven R3.
// ---------------------------------------------------------------------------
__device__ __forceinline__ void set_bit_s(unsigned* arr, int x, int y) {
    int p = x + 2;
    atomicOr(&arr[y * 4 + (p >> 5)], 1u << (p & 31));
}

__global__ void __launch_bounds__(1024, 1) nms_kernel(const float* __restrict__ cls) {
    __shared__ float    sc[NN];
    __shared__ unsigned dec1[WW * 4], kept1[WW * 4], dec2[WW * 4], kept2[WW * 4];

    const int t  = threadIdx.x;
    const int tx = t & 31, ty = t >> 5;
    const int x0 = 3 * tx, y0 = 3 * ty;
    const int w  = x0 >> 5, sh = x0 & 31;

    if (t < WW * 4) { dec1[t] = 0; kept1[t] = 0; dec2[t] = 0; kept2[t] = 0; }
    #pragma unroll
    for (int k = 0; k < 9; k++) sc[t + k * 1024] = cls[t + k * 1024];
    __syncthreads();

    // ---- Build masks + init invalid cells ----
    unsigned m1[9];
    unsigned long long m2all = 0;   // 4 bits/cell: up,left,right,down (thr 0.7)
    unsigned pend = 0;
    #pragma unroll
    for (int k = 0; k < 9; k++) {
        int ry = k / 3, cx = k % 3;
        int x = x0 + cx, y = y0 + ry;
        int c = y * WW + x;
        float s = sc[c];
        unsigned mm1 = 0, n2 = 0;
        if (s > 0.6f) {
            pend |= 1u << k;
            int xm = x % 3, ym = y % 3;
            #define EARLIER(n) (sc[(n)] > s || (sc[(n)] == s && (n) < c))
            if (x > 0  && EARLIER(c - 1))  { mm1 |= 1u << 11; if (xm != 2) n2 |= 2u; }
            if (x < 95 && EARLIER(c + 1))  { mm1 |= 1u << 13; if (xm != 1) n2 |= 4u; }
            if (y > 0  && EARLIER(c - 96)) { mm1 |= 1u << 7;  if (ym != 2) n2 |= 1u; }
            if (y < 95 && EARLIER(c + 96)) { mm1 |= 1u << 17; if (ym != 1) n2 |= 8u; }
            if (x > 1  && xm == 1 && EARLIER(c - 2))   mm1 |= 1u << 10;
            if (x < 94 && xm == 2 && EARLIER(c + 2))   mm1 |= 1u << 14;
            if (y > 1  && ym == 1 && EARLIER(c - 192)) mm1 |= 1u << 2;
            if (y < 94 && ym == 2 && EARLIER(c + 192)) mm1 |= 1u << 22;
            bool sxp4 = (xm == 1), sxm4 = (xm == 2), syp4 = (ym == 1), sym4 = (ym == 2);
            if (x > 0  && y > 0  && !(sxm4 && sym4) && EARLIER(c - 97)) mm1 |= 1u << 6;
            if (x < 95 && y > 0  && !(sxp4 && sym4) && EARLIER(c - 95)) mm1 |= 1u << 8;
            if (x > 0  && y < 95 && !(sxm4 && syp4) && EARLIER(c + 95)) mm1 |= 1u << 16;
            if (x < 95 && y < 95 && !(sxp4 && syp4) && EARLIER(c + 97)) mm1 |= 1u << 18;
            #undef EARLIER
        } else {
            set_bit_s(dec1, x, y);
            set_bit_s(dec2, x, y);
        }
        m1[k] = mm1;
        m2all |= (unsigned long long)n2 << (4 * k);
    }
    __syncthreads();

    unsigned p1 = pend, p2 = pend, keep9 = 0;

    // ---- Barrier rounds ----
    for (;;) {
        #pragma unroll
        for (int rep = 0; rep < 2; rep++) {
            // pass-1 sweep
            if (p1) {
                unsigned dw[7], kw[7];
                #pragma unroll
                for (int r = 0; r < 7; r++) {
                    int ry = y0 - 2 + r;
                    if ((unsigned)ry < WW) {
                        int base = ry * 4 + w;
                        dw[r] = __funnelshift_r(dec1[base],  dec1[base + 1],  sh) & 0x1FFu;
                        kw[r] = __funnelshift_r(kept1[base], kept1[base + 1], sh) & 0x1FFu;
                    } else { dw[r] = 0; kw[r] = 0; }
                }
                #pragma unroll
                for (int k = 0; k < 9; k++) {
                    if (!(p1 & (1u << k))) continue;
                    int ry = k / 3, cx = k % 3;
                    unsigned mm = m1[k], supp = 0, und = 0;
                    #pragma unroll
                    for (int r = 0; r < 5; r++) {
                        unsigned mrow = (mm >> (5 * r)) & 31u;
                        supp |= mrow & (kw[ry + r] >> cx);
                        und  |= mrow & ((~dw[ry + r]) >> cx);
                    }
                    int x = x0 + cx, y = y0 + ry;
                    if (supp) {
                        set_bit_s(dec1, x, y); set_bit_s(dec2, x, y);
                        dw[ry + 2] |= 1u << (cx + 2);
                        p1 &= ~(1u << k); p2 &= ~(1u << k);
                    } else if (!und) {
                        set_bit_s(dec1, x, y); set_bit_s(kept1, x, y);
                        dw[ry + 2] |= 1u << (cx + 2);
                        kw[ry + 2] |= 1u << (cx + 2);
                        p1 &= ~(1u << k);
                    }
                }
            }
            // pass-2 sweep (cells kept in pass 1)
            unsigned ready = p2 & ~p1;
            if (ready) {
                unsigned dw[7], kw[7];
                #pragma unroll
                for (int r = 0; r < 7; r++) {
                    int ry = y0 - 2 + r;
                    if ((unsigned)ry < WW) {
                        int base = ry * 4 + w;
                        dw[r] = __funnelshift_r(dec2[base],  dec2[base + 1],  sh) & 0x1FFu;
                        kw[r] = __funnelshift_r(kept2[base], kept2[base + 1], sh) & 0x1FFu;
                    } else { dw[r] = 0; kw[r] = 0; }
                }
                #pragma unroll
                for (int k = 0; k < 9; k++) {
                    if (!(ready & (1u << k))) continue;
                    int ry = k / 3, cx = k % 3;
                    unsigned n2 = (unsigned)(m2all >> (4 * k)) & 15u;
                    unsigned supp =
                          ((n2 >> 0) & (kw[ry + 1] >> (cx + 2)))
                        | ((n2 >> 1) & (kw[ry + 2] >> (cx + 1)))
                        | ((n2 >> 2) & (kw[ry + 2] >> (cx + 3)))
                        | ((n2 >> 3) & (kw[ry + 3] >> (cx + 2)));
                    unsigned und =
                          ((n2 >> 0) & ((~dw[ry + 1]) >> (cx + 2)))
                        | ((n2 >> 1) & ((~dw[ry + 2]) >> (cx + 1)))
                        | ((n2 >> 2) & ((~dw[ry + 2]) >> (cx + 3)))
                        | ((n2 >> 3) & ((~dw[ry + 3]) >> (cx + 2)));
                    int x = x0 + cx, y = y0 + ry;
                    if (supp & 1u) {
                        set_bit_s(dec2, x, y);
                        dw[ry + 2] |= 1u << (cx + 2);
                        p2 &= ~(1u << k);
                    } else if (!(und & 1u)) {
                        set_bit_s(dec2, x, y); set_bit_s(kept2, x, y);
                        dw[ry + 2] |= 1u << (cx + 2);
                        kw[ry + 2] |= 1u << (cx + 2);
                        keep9 |= 1u << k;
                        p2 &= ~(1u << k);
                    }
                }
            }
        }
        if (__syncthreads_and((p1 | p2) == 0)) break;
    }

    #pragma unroll
    for (int k = 0; k < 9; k++) {
        int c = (y0 + k / 3) * WW + x0 + (k % 3);
        g_keep[c] = (keep9 >> k) & 1u;
    }
}

// ---------------------------------------------------------------------------
// Epilogue (proven R3)
// ---------------------------------------------------------------------------
__global__ void __launch_bounds__(256) epi_kernel(const float* __restrict__ cls,
                                                  const float* __restrict__ reg,
                                                  float* __restrict__ out) {
    const int c = blockIdx.x * 256 + threadIdx.x;
    float s  = cls[c];
    int bin  = min((int)(s * 8192.0f), NB - 1);
    unsigned rank = g_binstart[bin];
    unsigned cnt  = min(g_bincnt[bin], (unsigned)CAP);
    for (unsigned j = 0; j < cnt; j++) {
        int idx = (int)g_list[bin * CAP + j];
        float sj = cls[idx];
        rank += (sj > s) || (sj == s && idx < c);
    }
    float kq = g_keep[c] ? 1.0f : 0.0f;
    int x = c % WW, y = c / WW;
    float X1 = rintf((2.0f * x) / 0.6f);
    float X2 = rintf((2.0f * x + 12.0f) / 0.6f);
    float Y1 = rintf((2.0f * y) / 0.6f);
    float Y2 = rintf((2.0f * y + 12.0f) / 0.6f);
    float bw = X2 - X1 + 1.0f;
    float bh = Y2 - Y1 + 1.0f;
    float4 d = ((const float4*)reg)[c];
    float* o = out + (int)rank * 5;
    o[0] = (X1 + d.x * bw) * kq;
    o[1] = (Y1 + d.y * bh) * kq;
    o[2] = (X2 + d.z * bw) * kq;
    o[3] = (Y2 + d.w * bh) * kq;
    o[4] = s * kq;
}

extern "C" void kernel_launch(void* const* d_in, const int* in_sizes, int n_in,
                              void* d_out, int out_size) {
    const float* cls = (const float*)d_in[0];
    const float* reg = (const float*)d_in[1];
    if (n_in >= 2 && in_sizes[0] > in_sizes[1]) {   // defensive: metadata order
        const float* t = cls; cls = reg; reg = t;
    }
    float* out = (float*)d_out;

    hist_kernel<<<36, 256>>>(cls);
    scan_kernel<<<1, 1024>>>();
    nms_kernel<<<1, 1024>>>(cls);
    epi_kernel<<<36, 256>>>(cls, reg, out);
}